// round 13
// baseline (speedup 1.0000x reference)
#include <cuda_runtime.h>
#include <math.h>
#include <stdint.h>

#define KEXP 8

// ---------------- scratch (static device memory; no allocations allowed) ----
__device__ float g_bufA[24780800];    // max: act1 = 128*64*55*55
__device__ float g_bufB[5971968];     // max: pool1 = 128*64*27*27
__device__ float g_wbuf[113246208];   // max: L4 mixed weights; FC scratch later
__device__ float g_pooled[128 * 384];
__device__ float g_r[128 * KEXP];

// FC scratch offsets inside g_wbuf (in floats)
#define POOLT_OFF 0
#define PART_OFF  (2*1024*1024)
#define Y1T_OFF   (7*1024*1024)
#define Y2T_OFF   (8*1024*1024)

// ---------------- packed fp32x2 FMA helpers ----------------------------------
__device__ __forceinline__ unsigned long long pack_dup_f32(float a) {
    unsigned long long p;
    asm("mov.b64 %0, {%1, %1};" : "=l"(p) : "f"(a));
    return p;
}
__device__ __forceinline__ void fma_f32x2(unsigned long long& d, unsigned long long a,
                                          unsigned long long b) {
    asm("fma.rn.f32x2 %0, %1, %2, %0;" : "+l"(d) : "l"(a), "l"(b));
}
__device__ __forceinline__ void unpack_f32x2(unsigned long long p, float& lo, float& hi) {
    asm("mov.b64 {%0, %1}, %2;" : "=f"(lo), "=f"(hi) : "l"(p));
}

// ---------------- per-channel global average pool ---------------------------
__global__ void pool_mean_kernel(const float* __restrict__ x, float* __restrict__ pooled,
                                 int Cin, int HW) {
    int c = blockIdx.x, b = blockIdx.y;
    const float* p = x + ((size_t)b * Cin + c) * HW;
    float s = 0.f;
    for (int i = threadIdx.x; i < HW; i += blockDim.x) s += p[i];
    __shared__ float sh[32];
    int lane = threadIdx.x & 31, w = threadIdx.x >> 5;
    #pragma unroll
    for (int o = 16; o > 0; o >>= 1) s += __shfl_down_sync(0xffffffffu, s, o);
    if (lane == 0) sh[w] = s;
    __syncthreads();
    if (w == 0) {
        s = (lane < (int)(blockDim.x >> 5)) ? sh[lane] : 0.f;
        #pragma unroll
        for (int o = 16; o > 0; o >>= 1) s += __shfl_down_sync(0xffffffffu, s, o);
        if (lane == 0) pooled[b * Cin + c] = s / (float)HW;
    }
}

// ---------------- routing ----------------------------------------------------
__global__ void routing_kernel(const float* __restrict__ pooled, const float* __restrict__ rw,
                               const float* __restrict__ rb, float* __restrict__ r, int Cin) {
    int b = blockIdx.x;
    int k = threadIdx.x >> 5, lane = threadIdx.x & 31;
    if (k < KEXP) {
        float s = 0.f;
        for (int c = lane; c < Cin; c += 32) s += pooled[b * Cin + c] * rw[c * KEXP + k];
        #pragma unroll
        for (int o = 16; o > 0; o >>= 1) s += __shfl_down_sync(0xffffffffu, s, o);
        if (lane == 0) r[b * KEXP + k] = 1.f / (1.f + expf(-(s + rb[k])));
    }
}

// ---------------- expert weight mixing (layer 1: original [ci][khw] order) ---
__global__ void mixw2_kernel(const float4* __restrict__ w, const float* __restrict__ r,
                             float4* __restrict__ wb, int ws4) {
    __shared__ float rs[8][KEXP];
    int bg = blockIdx.y;
    if (threadIdx.x < 64)
        rs[threadIdx.x >> 3][threadIdx.x & 7] =
            r[(bg * 8 + (threadIdx.x >> 3)) * KEXP + (threadIdx.x & 7)];
    __syncthreads();
    int i = blockIdx.x * blockDim.x + threadIdx.x;
    if (i >= ws4) return;
    float4 wv[KEXP];
    #pragma unroll
    for (int k = 0; k < KEXP; k++) wv[k] = w[(size_t)k * ws4 + i];
    #pragma unroll
    for (int bb = 0; bb < 8; bb++) {
        float4 acc = make_float4(0.f, 0.f, 0.f, 0.f);
        #pragma unroll
        for (int k = 0; k < KEXP; k++) {
            float rk = rs[bb][k];
            acc.x += rk * wv[k].x; acc.y += rk * wv[k].y;
            acc.z += rk * wv[k].z; acc.w += rk * wv[k].w;
        }
        wb[(size_t)(bg * 8 + bb) * ws4 + i] = acc;
    }
}

// ---------------- mixing + K-transpose, read-once over full batch ------------
// in:  w[k][co][ci][khw]   out: wb[b][co][khw*Cin + ci]  (khw-major, ci fastest)
__global__ void __launch_bounds__(256) mixw4_kernel(
    const float* __restrict__ w, const float* __restrict__ r,
    float* __restrict__ wb, int Cout, int Cin, int KHW) {
    const int Ksz = Cin * KHW;
    const int co = blockIdx.y;
    const int o = blockIdx.x * 512 + threadIdx.x * 2;

    __shared__ float rs[128][KEXP];
    for (int i = threadIdx.x; i < 128 * KEXP; i += 256)
        rs[i >> 3][i & 7] = r[i];
    __syncthreads();

    if (o >= Ksz) return;
    const bool has2 = (o + 1) < Ksz;

    const int khw0 = o / Cin, ci0 = o - khw0 * Cin;
    const int khw1 = (o + 1) / Cin, ci1 = (o + 1) - khw1 * Cin;
    const size_t ws = (size_t)Cout * Ksz;
    const float* p0 = w + (size_t)co * Ksz + (size_t)ci0 * KHW + khw0;
    const float* p1 = w + (size_t)co * Ksz + (size_t)ci1 * KHW + khw1;

    float wv0[KEXP], wv1[KEXP];
    #pragma unroll
    for (int k = 0; k < KEXP; k++) {
        wv0[k] = p0[(size_t)k * ws];
        wv1[k] = has2 ? p1[(size_t)k * ws] : 0.f;
    }

    float* out0 = wb + (size_t)co * Ksz + o;
    const size_t bstride = (size_t)Cout * Ksz;
    for (int b = 0; b < 128; b++) {
        float a0 = 0.f, a1 = 0.f;
        #pragma unroll
        for (int k = 0; k < KEXP; k++) {
            float rk = rs[b][k];
            a0 += rk * wv0[k];
            a1 += rk * wv1[k];
        }
        float* out = out0 + (size_t)b * bstride;
        if (has2) *reinterpret_cast<float2*>(out) = make_float2(a0, a1);
        else out[0] = a0;
    }
}

// ============================================================================
// SIMT conv implicit GEMM, f32x2 FMA, double-buffered (R3/R8 proven core).
// CIN_INNER: mixed weights are [khw][ci]; every BK=16 chunk lies in ONE (ky,kx).
// ============================================================================
template <int BM, int BN, int KH, int KW, int S, int P, bool AVEC, bool CIN_INNER>
__global__ void __launch_bounds__(128) conv2_kernel(
    const float* __restrict__ X, const float* __restrict__ WB,
    const float* __restrict__ R, const float* __restrict__ BEXP,
    float* __restrict__ Y, int Cin, int Cout, int H, int W, int OH, int OW) {
    constexpr int BK = 16, TM = 8, TN = 8;
    constexpr int TH = BM * BN / (TM * TN);   // 128
    constexpr int KHW = KH * KW;
    constexpr int A4 = BM * BK / (4 * TH);
    constexpr int BL = BN * BK / TH;
    constexpr int BKP = TH / BN;

    __shared__ float As[2][BK][BM + 4];
    __shared__ float Bs[2][BK][BN + 4];

    const int b = blockIdx.z;
    const int m0 = blockIdx.y * BM, n0 = blockIdx.x * BN;
    const int Ksz = Cin * KHW;
    const int Nn = OH * OW;
    const int HWp = H * W;
    const int tid = threadIdx.x;

    const float* __restrict__ Xb = X + (size_t)b * Cin * HWp;
    const float* __restrict__ Wb = WB + (size_t)b * Cout * Ksz;

    const int nb = tid % BN;
    const int gnb = n0 + nb;
    const bool nv = gnb < Nn;
    const int oyb = nv ? gnb / OW : 0;
    const int oxb = nv ? gnb - oyb * OW : 0;
    const int iy0 = oyb * S - P, ix0 = oxb * S - P;
    const int kb0 = tid / BN;

    float4 aT[A4];
    float bT[BL];

    auto ldg = [&](int kk) {
        #pragma unroll
        for (int p = 0; p < A4; p++) {
            int e = tid + p * TH;
            int m = e >> 2, gk = kk + (e & 3) * 4;
            float4 v = make_float4(0.f, 0.f, 0.f, 0.f);
            if (m0 + m < Cout) {
                if (AVEC && (CIN_INNER || gk + 3 < Ksz)) {
                    v = *reinterpret_cast<const float4*>(Wb + (size_t)(m0 + m) * Ksz + gk);
                } else {
                    float* pv = (float*)&v;
                    #pragma unroll
                    for (int i = 0; i < 4; i++)
                        if (gk + i < Ksz) pv[i] = Wb[(size_t)(m0 + m) * Ksz + gk + i];
                }
            }
            aT[p] = v;
        }
        if (CIN_INNER) {
            int khw = kk / Cin;
            int ci0 = kk - khw * Cin;
            int ky = khw / KW, kx = khw - ky * KW;
            int iy = iy0 + ky, ix = ix0 + kx;
            bool rowv = nv && iy >= 0 && iy < H && ix >= 0 && ix < W;
            const float* src = Xb + (size_t)iy * W + ix;
            #pragma unroll
            for (int p = 0; p < BL; p++) {
                int ci = ci0 + kb0 + p * BKP;
                bT[p] = rowv ? src[(size_t)ci * HWp] : 0.f;
            }
        } else {
            #pragma unroll
            for (int p = 0; p < BL; p++) {
                int k = kb0 + p * BKP;
                int gk = kk + k;
                float v = 0.f;
                if (nv && gk < Ksz) {
                    int ci = gk / KHW;
                    int rem = gk - ci * KHW;
                    int ky = rem / KW, kx = rem - ky * KW;
                    int iy = iy0 + ky, ix = ix0 + kx;
                    if (iy >= 0 && iy < H && ix >= 0 && ix < W)
                        v = Xb[((size_t)ci * H + iy) * W + ix];
                }
                bT[p] = v;
            }
        }
    };
    auto sts = [&](int buf) {
        #pragma unroll
        for (int p = 0; p < A4; p++) {
            int e = tid + p * TH;
            int m = e >> 2, k = (e & 3) * 4;
            As[buf][k + 0][m] = aT[p].x;
            As[buf][k + 1][m] = aT[p].y;
            As[buf][k + 2][m] = aT[p].z;
            As[buf][k + 3][m] = aT[p].w;
        }
        #pragma unroll
        for (int p = 0; p < BL; p++) Bs[buf][kb0 + p * BKP][nb] = bT[p];
    };

    const int tx = tid % (BN / TN);
    const int ty = tid / (BN / TN);

    unsigned long long acc2[TM][TN / 2];
    #pragma unroll
    for (int i = 0; i < TM; i++)
        #pragma unroll
        for (int j = 0; j < TN / 2; j++) acc2[i][j] = 0ull;

    const int nT = (Ksz + BK - 1) / BK;
    ldg(0);
    sts(0);
    __syncthreads();

    for (int kt = 0; kt < nT; kt++) {
        int cur = kt & 1;
        if (kt + 1 < nT) ldg((kt + 1) * BK);
        #pragma unroll
        for (int kq = 0; kq < BK; kq++) {
            float4 a0 = *(const float4*)&As[cur][kq][ty * TM];
            float4 a1 = *(const float4*)&As[cur][kq][ty * TM + 4];
            const ulonglong2* pb = (const ulonglong2*)&Bs[cur][kq][tx * TN];
            ulonglong2 q0 = pb[0], q1 = pb[1];
            unsigned long long b2[4] = {q0.x, q0.y, q1.x, q1.y};
            float ar[8] = {a0.x, a0.y, a0.z, a0.w, a1.x, a1.y, a1.z, a1.w};
            #pragma unroll
            for (int i = 0; i < TM; i++) {
                unsigned long long af = pack_dup_f32(ar[i]);
                #pragma unroll
                for (int j = 0; j < TN / 2; j++) fma_f32x2(acc2[i][j], af, b2[j]);
            }
        }
        if (kt + 1 < nT) {
            sts(cur ^ 1);
            __syncthreads();
        }
    }

    float rr[KEXP];
    #pragma unroll
    for (int k = 0; k < KEXP; k++) rr[k] = R[b * KEXP + k];
    #pragma unroll
    for (int i = 0; i < TM; i++) {
        int gm = m0 + ty * TM + i;
        if (gm < Cout) {
            float bias = 0.f;
            #pragma unroll
            for (int k = 0; k < KEXP; k++) bias += rr[k] * BEXP[k * Cout + gm];
            float* Yp = Y + ((size_t)b * Cout + gm) * Nn;
            #pragma unroll
            for (int j = 0; j < TN / 2; j++) {
                float lo, hi;
                unpack_f32x2(acc2[i][j], lo, hi);
                int gn = n0 + tx * TN + 2 * j;
                if (gn < Nn) {
                    float v = lo + bias;
                    Yp[gn] = v > 0.f ? v : 0.f;
                }
                if (gn + 1 < Nn) {
                    float v = hi + bias;
                    Yp[gn + 1] = v > 0.f ? v : 0.f;
                }
            }
        }
    }
}

// ---------------- FC split-K partial GEMM (transposed, f32x2) ---------------
__global__ void __launch_bounds__(256) fc_partial_kernel(
    const float* __restrict__ Wm, const float* __restrict__ Xt,
    float* __restrict__ Part, int Nout, int Npad, int Kchunk) {
    constexpr int BM = 128, BN = 128, BK = 16, TM = 8, TN = 8;
    __shared__ float As[2][BK][BM + 4];
    __shared__ float Bs[2][BK][BN + 4];
    const int m0 = blockIdx.x * BM;
    const int ks = blockIdx.y;
    const int kbase = ks * Kchunk;
    const int tid = threadIdx.x;

    const int ma = tid % BM;
    const int ka = tid / BM;
    const bool mvalid = (m0 + ma) < Nout;

    float aT[8], bT[8];
    auto ldg = [&](int kk) {
        #pragma unroll
        for (int p = 0; p < 8; p++) {
            int gk = kbase + kk + ka + 2 * p;
            aT[p] = mvalid ? Wm[(size_t)gk * Nout + m0 + ma] : 0.f;
            bT[p] = Xt[(size_t)gk * 128 + ma];
        }
    };
    auto sts = [&](int buf) {
        #pragma unroll
        for (int p = 0; p < 8; p++) {
            int k = ka + 2 * p;
            As[buf][k][ma] = aT[p];
            Bs[buf][k][ma] = bT[p];
        }
    };

    const int tx = tid % (BN / TN);
    const int ty = tid / (BN / TN);
    unsigned long long acc2[TM][TN / 2];
    #pragma unroll
    for (int i = 0; i < TM; i++)
        #pragma unroll
        for (int j = 0; j < TN / 2; j++) acc2[i][j] = 0ull;

    const int nT = Kchunk / BK;
    ldg(0);
    sts(0);
    __syncthreads();
    for (int kt = 0; kt < nT; kt++) {
        int cur = kt & 1;
        if (kt + 1 < nT) ldg((kt + 1) * BK);
        #pragma unroll
        for (int kq = 0; kq < BK; kq++) {
            float4 a0 = *(const float4*)&As[cur][kq][ty * TM];
            float4 a1 = *(const float4*)&As[cur][kq][ty * TM + 4];
            const ulonglong2* pb = (const ulonglong2*)&Bs[cur][kq][tx * TN];
            ulonglong2 q0 = pb[0], q1 = pb[1];
            unsigned long long b2[4] = {q0.x, q0.y, q1.x, q1.y};
            float ar[8] = {a0.x, a0.y, a0.z, a0.w, a1.x, a1.y, a1.z, a1.w};
            #pragma unroll
            for (int i = 0; i < TM; i++) {
                unsigned long long af = pack_dup_f32(ar[i]);
                #pragma unroll
                for (int j = 0; j < TN / 2; j++) fma_f32x2(acc2[i][j], af, b2[j]);
            }
        }
        if (kt + 1 < nT) {
            sts(cur ^ 1);
            __syncthreads();
        }
    }
    #pragma unroll
    for (int i = 0; i < TM; i++) {
        size_t rrow = (size_t)ks * Npad + m0 + ty * TM + i;
        #pragma unroll
        for (int j = 0; j < TN / 2; j++) {
            float lo, hi;
            unpack_f32x2(acc2[i][j], lo, hi);
            Part[rrow * 128 + tx * TN + 2 * j] = lo;
            Part[rrow * 128 + tx * TN + 2 * j + 1] = hi;
        }
    }
}

__global__ void fc_reduce_kernel(const float* __restrict__ Part, const float* __restrict__ bias,
                                 float* __restrict__ Yt, int Nout, int Npad, int S) {
    int idx = blockIdx.x * blockDim.x + threadIdx.x;
    if (idx >= Nout * 128) return;
    int n = idx >> 7, bb = idx & 127;
    float s = 0.f;
    for (int si = 0; si < S; si++) s += Part[((size_t)si * Npad + n) * 128 + bb];
    float v = s + bias[n];
    Yt[idx] = v > 0.f ? v : 0.f;
}

__global__ void fc_reduce_out_kernel(const float* __restrict__ Part, const float* __restrict__ bias,
                                     float* __restrict__ out, int Nout, int Npad, int S) {
    int idx = blockIdx.x * blockDim.x + threadIdx.x;
    if (idx >= Nout * 128) return;
    int n = idx >> 7, bb = idx & 127;
    float s = 0.f;
    for (int si = 0; si < S; si++) s += Part[((size_t)si * Npad + n) * 128 + bb];
    out[(size_t)bb * Nout + n] = s + bias[n];
}

// ---------------- maxpools ---------------------------------------------------
// fused 3x2 maxpool + per-(b,c) mean of the pooled output (deterministic)
__global__ void maxpool_mean_kernel(const float* __restrict__ x, float* __restrict__ y,
                                    float* __restrict__ pooled,
                                    int C, int H, int W, int OH, int OW) {
    int c = blockIdx.x, b = blockIdx.y;
    const float* p = x + ((size_t)b * C + c) * H * W;
    float* yp = y + ((size_t)b * C + c) * OH * OW;
    const int total = OH * OW;
    float s = 0.f;
    for (int i = threadIdx.x; i < total; i += blockDim.x) {
        int oy = i / OW, ox = i - oy * OW;
        const float* q = p + (size_t)(oy * 2) * W + ox * 2;
        float m = -INFINITY;
        #pragma unroll
        for (int ii = 0; ii < 3; ii++)
            #pragma unroll
            for (int jj = 0; jj < 3; jj++) {
                float v = q[ii * W + jj];
                m = v > m ? v : m;
            }
        yp[i] = m;
        s += m;
    }
    __shared__ float sh[32];
    int lane = threadIdx.x & 31, w = threadIdx.x >> 5;
    #pragma unroll
    for (int o = 16; o > 0; o >>= 1) s += __shfl_down_sync(0xffffffffu, s, o);
    if (lane == 0) sh[w] = s;
    __syncthreads();
    if (w == 0) {
        s = (lane < (int)(blockDim.x >> 5)) ? sh[lane] : 0.f;
        #pragma unroll
        for (int o = 16; o > 0; o >>= 1) s += __shfl_down_sync(0xffffffffu, s, o);
        if (lane == 0) pooled[b * C + c] = s / (float)total;
    }
}

__global__ void maxpoolT_kernel(const float* __restrict__ x, float* __restrict__ yt,
                                int C, int H, int W, int OH, int OW) {
    int idx = blockIdx.x * blockDim.x + threadIdx.x;
    int total = 128 * C * OH * OW;
    if (idx >= total) return;
    int ox = idx % OW; int t = idx / OW;
    int oy = t % OH; t /= OH;
    int c = t % C; int b = t / C;
    const float* p = x + (((size_t)b * C + c) * H + oy * 2) * W + ox * 2;
    float m = -INFINITY;
    #pragma unroll
    for (int i = 0; i < 3; i++)
        #pragma unroll
        for (int j = 0; j < 3; j++) {
            float v = p[i * W + j];
            m = v > m ? v : m;
        }
    yt[((size_t)(c * OH + oy) * OW + ox) * 128 + b] = m;
}

// ---------------- driver -----------------------------------------------------
static inline int ceil_div(int a, int b) { return (a + b - 1) / b; }

extern "C" void kernel_launch(void* const* d_in, const int* in_sizes, int n_in,
                              void* d_out, int out_size) {
    const float* x = (const float*)d_in[0];
    const float *w[5], *bexp[5], *rw[5], *rb[5];
    for (int l = 0; l < 5; l++) {
        w[l]    = (const float*)d_in[1 + 4 * l];
        bexp[l] = (const float*)d_in[2 + 4 * l];
        rw[l]   = (const float*)d_in[3 + 4 * l];
        rb[l]   = (const float*)d_in[4 + 4 * l];
    }
    const float* fw1 = (const float*)d_in[21]; const float* fb1 = (const float*)d_in[22];
    const float* fw2 = (const float*)d_in[23]; const float* fb2 = (const float*)d_in[24];
    const float* fw3 = (const float*)d_in[25]; const float* fb3 = (const float*)d_in[26];

    float *bufA, *bufB, *wbuf, *pooled, *r;
    cudaGetSymbolAddress((void**)&bufA, g_bufA);
    cudaGetSymbolAddress((void**)&bufB, g_bufB);
    cudaGetSymbolAddress((void**)&wbuf, g_wbuf);
    cudaGetSymbolAddress((void**)&pooled, g_pooled);
    cudaGetSymbolAddress((void**)&r, g_r);

    const int B = 128;

    // ===== Layer 1: CondConv 3->64, k=11, s=4, p=2 : 224->55, pool(+mean)->27
    pool_mean_kernel<<<dim3(3, B), 256>>>(x, pooled, 3, 224 * 224);
    routing_kernel<<<B, 256>>>(pooled, rw[0], rb[0], r, 3);
    {
        int ws4 = 64 * 3 * 121 / 4;
        mixw2_kernel<<<dim3(ceil_div(ws4, 256), B / 8), 256>>>((const float4*)w[0], r, (float4*)wbuf, ws4);
    }
    conv2_kernel<64, 128, 11, 11, 4, 2, false, false><<<dim3(24, 1, B), 128>>>(
        x, wbuf, r, bexp[0], bufA, 3, 64, 224, 224, 55, 55);
    maxpool_mean_kernel<<<dim3(64, B), 256>>>(bufA, bufB, pooled, 64, 55, 55, 27, 27);

    // ===== Layer 2: CondConv 64->192, k=5, p=2 : 27->27, pool(+mean)->13
    routing_kernel<<<B, 256>>>(pooled, rw[1], rb[1], r, 64);
    mixw4_kernel<<<dim3(ceil_div(64 * 25, 512), 192), 256>>>(w[1], r, wbuf, 192, 64, 25);
    conv2_kernel<64, 128, 5, 5, 1, 2, true, true><<<dim3(6, 3, B), 128>>>(
        bufB, wbuf, r, bexp[1], bufA, 64, 192, 27, 27, 27, 27);
    maxpool_mean_kernel<<<dim3(192, B), 256>>>(bufA, bufB, pooled, 192, 27, 27, 13, 13);

    // ===== Layer 3: CondConv 192->384, k=3, p=1 : 13->13
    routing_kernel<<<B, 256>>>(pooled, rw[2], rb[2], r, 192);
    mixw4_kernel<<<dim3(ceil_div(192 * 9, 512), 384), 256>>>(w[2], r, wbuf, 384, 192, 9);
    conv2_kernel<128, 64, 3, 3, 1, 1, true, true><<<dim3(3, 3, B), 128>>>(
        bufB, wbuf, r, bexp[2], bufA, 192, 384, 13, 13, 13, 13);

    // ===== Layer 4: CondConv 384->256, k=3, p=1 : 13->13
    pool_mean_kernel<<<dim3(384, B), 192>>>(bufA, pooled, 384, 13 * 13);
    routing_kernel<<<B, 256>>>(pooled, rw[3], rb[3], r, 384);
    mixw4_kernel<<<dim3(ceil_div(384 * 9, 512), 256), 256>>>(w[3], r, wbuf, 256, 384, 9);
    conv2_kernel<128, 64, 3, 3, 1, 1, true, true><<<dim3(3, 2, B), 128>>>(
        bufA, wbuf, r, bexp[3], bufB, 384, 256, 13, 13, 13, 13);

    // ===== Layer 5: CondConv 256->256, k=3, p=1 : 13->13, pool->6
    pool_mean_kernel<<<dim3(256, B), 192>>>(bufB, pooled, 256, 13 * 13);
    routing_kernel<<<B, 256>>>(pooled, rw[4], rb[4], r, 256);
    mixw4_kernel<<<dim3(ceil_div(256 * 9, 512), 256), 256>>>(w[4], r, wbuf, 256, 256, 9);
    conv2_kernel<128, 64, 3, 3, 1, 1, true, true><<<dim3(3, 2, B), 128>>>(
        bufB, wbuf, r, bexp[4], bufA, 256, 256, 13, 13, 13, 13);

    // final pool -> transposed activations [9216][128]
    maxpoolT_kernel<<<ceil_div(B * 256 * 36, 256), 256>>>(bufA, wbuf + POOLT_OFF, 256, 13, 13, 6, 6);

    // ===== FC head (fp32, split-K, S=4) =====================================
    fc_partial_kernel<<<dim3(32, 4), 256>>>(fw1, wbuf + POOLT_OFF, wbuf + PART_OFF,
                                            4096, 4096, 2304);
    fc_reduce_kernel<<<ceil_div(4096 * 128, 256), 256>>>(wbuf + PART_OFF, fb1,
                                                         wbuf + Y1T_OFF, 4096, 4096, 4);
    fc_partial_kernel<<<dim3(32, 4), 256>>>(fw2, wbuf + Y1T_OFF, wbuf + PART_OFF,
                                            4096, 4096, 1024);
    fc_reduce_kernel<<<ceil_div(4096 * 128, 256), 256>>>(wbuf + PART_OFF, fb2,
                                                         wbuf + Y2T_OFF, 4096, 4096, 4);
    fc_partial_kernel<<<dim3(8, 4), 256>>>(fw3, wbuf + Y2T_OFF, wbuf + PART_OFF,
                                           1000, 1024, 1024);
    fc_reduce_out_kernel<<<ceil_div(1000 * 128, 256), 256>>>(wbuf + PART_OFF, fb3,
                                                             (float*)d_out, 1000, 1024, 4);
}

// round 15
// speedup vs baseline: 1.4097x; 1.4097x over previous
#include <cuda_runtime.h>
#include <math.h>
#include <stdint.h>

#define KEXP 8

// ---------------- scratch (static device memory; no allocations allowed) ----
__device__ float g_bufA[24780800];    // max: act1 = 128*64*55*55
__device__ float g_bufB[5971968];     // max: pool1 = 128*64*27*27
__device__ float g_wbuf[113246208];   // max: L4 mixed weights; FC scratch later
__device__ float g_pooled[128 * 384];
__device__ float g_r[128 * KEXP];

// FC scratch offsets inside g_wbuf (in floats)
#define POOLT_OFF 0
#define PART_OFF  (2*1024*1024)
#define Y1T_OFF   (7*1024*1024)
#define Y2T_OFF   (8*1024*1024)

// ---------------- packed fp32x2 FMA helpers ----------------------------------
__device__ __forceinline__ unsigned long long pack_dup_f32(float a) {
    unsigned long long p;
    asm("mov.b64 %0, {%1, %1};" : "=l"(p) : "f"(a));
    return p;
}
__device__ __forceinline__ void fma_f32x2(unsigned long long& d, unsigned long long a,
                                          unsigned long long b) {
    asm("fma.rn.f32x2 %0, %1, %2, %0;" : "+l"(d) : "l"(a), "l"(b));
}
__device__ __forceinline__ void unpack_f32x2(unsigned long long p, float& lo, float& hi) {
    asm("mov.b64 {%0, %1}, %2;" : "=f"(lo), "=f"(hi) : "l"(p));
}

// ---------------- per-channel global average pool ---------------------------
__global__ void pool_mean_kernel(const float* __restrict__ x, float* __restrict__ pooled,
                                 int Cin, int HW) {
    int c = blockIdx.x, b = blockIdx.y;
    const float* p = x + ((size_t)b * Cin + c) * HW;
    float s = 0.f;
    for (int i = threadIdx.x; i < HW; i += blockDim.x) s += p[i];
    __shared__ float sh[32];
    int lane = threadIdx.x & 31, w = threadIdx.x >> 5;
    #pragma unroll
    for (int o = 16; o > 0; o >>= 1) s += __shfl_down_sync(0xffffffffu, s, o);
    if (lane == 0) sh[w] = s;
    __syncthreads();
    if (w == 0) {
        s = (lane < (int)(blockDim.x >> 5)) ? sh[lane] : 0.f;
        #pragma unroll
        for (int o = 16; o > 0; o >>= 1) s += __shfl_down_sync(0xffffffffu, s, o);
        if (lane == 0) pooled[b * Cin + c] = s / (float)HW;
    }
}

// ---------------- routing ----------------------------------------------------
__global__ void routing_kernel(const float* __restrict__ pooled, const float* __restrict__ rw,
                               const float* __restrict__ rb, float* __restrict__ r, int Cin) {
    int b = blockIdx.x;
    int k = threadIdx.x >> 5, lane = threadIdx.x & 31;
    if (k < KEXP) {
        float s = 0.f;
        for (int c = lane; c < Cin; c += 32) s += pooled[b * Cin + c] * rw[c * KEXP + k];
        #pragma unroll
        for (int o = 16; o > 0; o >>= 1) s += __shfl_down_sync(0xffffffffu, s, o);
        if (lane == 0) r[b * KEXP + k] = 1.f / (1.f + expf(-(s + rb[k])));
    }
}

// ---------------- expert weight mixing (layer 1: original [ci][khw] order) ---
__global__ void mixw2_kernel(const float4* __restrict__ w, const float* __restrict__ r,
                             float4* __restrict__ wb, int ws4) {
    __shared__ float rs[8][KEXP];
    int bg = blockIdx.y;
    if (threadIdx.x < 64)
        rs[threadIdx.x >> 3][threadIdx.x & 7] =
            r[(bg * 8 + (threadIdx.x >> 3)) * KEXP + (threadIdx.x & 7)];
    __syncthreads();
    int i = blockIdx.x * blockDim.x + threadIdx.x;
    if (i >= ws4) return;
    float4 wv[KEXP];
    #pragma unroll
    for (int k = 0; k < KEXP; k++) wv[k] = w[(size_t)k * ws4 + i];
    #pragma unroll
    for (int bb = 0; bb < 8; bb++) {
        float4 acc = make_float4(0.f, 0.f, 0.f, 0.f);
        #pragma unroll
        for (int k = 0; k < KEXP; k++) {
            float rk = rs[bb][k];
            acc.x += rk * wv[k].x; acc.y += rk * wv[k].y;
            acc.z += rk * wv[k].z; acc.w += rk * wv[k].w;
        }
        wb[(size_t)(bg * 8 + bb) * ws4 + i] = acc;
    }
}

// ---------------- mixing + K-transpose, read-once over full batch ------------
// in:  w[k][co][ci][khw]   out: wb[b][co][khw*Cin + ci]  (khw-major, ci fastest)
__global__ void __launch_bounds__(256) mixw4_kernel(
    const float* __restrict__ w, const float* __restrict__ r,
    float* __restrict__ wb, int Cout, int Cin, int KHW) {
    const int Ksz = Cin * KHW;
    const int co = blockIdx.y;
    const int o = blockIdx.x * 512 + threadIdx.x * 2;

    __shared__ float rs[128][KEXP];
    for (int i = threadIdx.x; i < 128 * KEXP; i += 256)
        rs[i >> 3][i & 7] = r[i];
    __syncthreads();

    if (o >= Ksz) return;
    const bool has2 = (o + 1) < Ksz;

    const int khw0 = o / Cin, ci0 = o - khw0 * Cin;
    const int khw1 = (o + 1) / Cin, ci1 = (o + 1) - khw1 * Cin;
    const size_t ws = (size_t)Cout * Ksz;
    const float* p0 = w + (size_t)co * Ksz + (size_t)ci0 * KHW + khw0;
    const float* p1 = w + (size_t)co * Ksz + (size_t)ci1 * KHW + khw1;

    float wv0[KEXP], wv1[KEXP];
    #pragma unroll
    for (int k = 0; k < KEXP; k++) {
        wv0[k] = p0[(size_t)k * ws];
        wv1[k] = has2 ? p1[(size_t)k * ws] : 0.f;
    }

    float* out0 = wb + (size_t)co * Ksz + o;
    const size_t bstride = (size_t)Cout * Ksz;
    for (int b = 0; b < 128; b++) {
        float a0 = 0.f, a1 = 0.f;
        #pragma unroll
        for (int k = 0; k < KEXP; k++) {
            float rk = rs[b][k];
            a0 += rk * wv0[k];
            a1 += rk * wv1[k];
        }
        float* out = out0 + (size_t)b * bstride;
        if (has2) *reinterpret_cast<float2*>(out) = make_float2(a0, a1);
        else out[0] = a0;
    }
}

// ============================================================================
// SIMT conv implicit GEMM, f32x2 FMA, double-buffered (R3/R8 proven core).
// CIN_INNER: mixed weights are [khw][ci]; every BK=16 chunk lies in ONE (ky,kx).
// TM parametrized (8 for BM=128 or BNx128 tiles, 4 for 64x64 tiles); TN = 8.
// ============================================================================
template <int BM, int BN, int TM, int KH, int KW, int S, int P, bool AVEC, bool CIN_INNER>
__global__ void __launch_bounds__(128) conv2_kernel(
    const float* __restrict__ X, const float* __restrict__ WB,
    const float* __restrict__ R, const float* __restrict__ BEXP,
    float* __restrict__ Y, int Cin, int Cout, int H, int W, int OH, int OW) {
    constexpr int BK = 16, TN = 8;
    constexpr int TH = BM * BN / (TM * TN);   // must be 128
    static_assert(TH == 128, "128 threads");
    constexpr int KHW = KH * KW;
    constexpr int A4 = BM * BK / (4 * TH);
    constexpr int BL = BN * BK / TH;
    constexpr int BKP = TH / BN;

    __shared__ float As[2][BK][BM + 4];
    __shared__ float Bs[2][BK][BN + 4];

    const int b = blockIdx.z;
    const int m0 = blockIdx.y * BM, n0 = blockIdx.x * BN;
    const int Ksz = Cin * KHW;
    const int Nn = OH * OW;
    const int HWp = H * W;
    const int tid = threadIdx.x;

    const float* __restrict__ Xb = X + (size_t)b * Cin * HWp;
    const float* __restrict__ Wb = WB + (size_t)b * Cout * Ksz;

    const int nb = tid % BN;
    const int gnb = n0 + nb;
    const bool nv = gnb < Nn;
    const int oyb = nv ? gnb / OW : 0;
    const int oxb = nv ? gnb - oyb * OW : 0;
    const int iy0 = oyb * S - P, ix0 = oxb * S - P;
    const int kb0 = tid / BN;

    float4 aT[A4];
    float bT[BL];

    auto ldg = [&](int kk) {
        #pragma unroll
        for (int p = 0; p < A4; p++) {
            int e = tid + p * TH;
            int m = e >> 2, gk = kk + (e & 3) * 4;
            float4 v = make_float4(0.f, 0.f, 0.f, 0.f);
            if (m0 + m < Cout) {
                if (AVEC && (CIN_INNER || gk + 3 < Ksz)) {
                    v = *reinterpret_cast<const float4*>(Wb + (size_t)(m0 + m) * Ksz + gk);
                } else {
                    float* pv = (float*)&v;
                    #pragma unroll
                    for (int i = 0; i < 4; i++)
                        if (gk + i < Ksz) pv[i] = Wb[(size_t)(m0 + m) * Ksz + gk + i];
                }
            }
            aT[p] = v;
        }
        if (CIN_INNER) {
            int khw = kk / Cin;
            int ci0 = kk - khw * Cin;
            int ky = khw / KW, kx = khw - ky * KW;
            int iy = iy0 + ky, ix = ix0 + kx;
            bool rowv = nv && iy >= 0 && iy < H && ix >= 0 && ix < W;
            const float* src = Xb + (size_t)iy * W + ix;
            #pragma unroll
            for (int p = 0; p < BL; p++) {
                int ci = ci0 + kb0 + p * BKP;
                bT[p] = rowv ? src[(size_t)ci * HWp] : 0.f;
            }
        } else {
            #pragma unroll
            for (int p = 0; p < BL; p++) {
                int k = kb0 + p * BKP;
                int gk = kk + k;
                float v = 0.f;
                if (nv && gk < Ksz) {
                    int ci = gk / KHW;
                    int rem = gk - ci * KHW;
                    int ky = rem / KW, kx = rem - ky * KW;
                    int iy = iy0 + ky, ix = ix0 + kx;
                    if (iy >= 0 && iy < H && ix >= 0 && ix < W)
                        v = Xb[((size_t)ci * H + iy) * W + ix];
                }
                bT[p] = v;
            }
        }
    };
    auto sts = [&](int buf) {
        #pragma unroll
        for (int p = 0; p < A4; p++) {
            int e = tid + p * TH;
            int m = e >> 2, k = (e & 3) * 4;
            As[buf][k + 0][m] = aT[p].x;
            As[buf][k + 1][m] = aT[p].y;
            As[buf][k + 2][m] = aT[p].z;
            As[buf][k + 3][m] = aT[p].w;
        }
        #pragma unroll
        for (int p = 0; p < BL; p++) Bs[buf][kb0 + p * BKP][nb] = bT[p];
    };

    const int tx = tid % (BN / TN);
    const int ty = tid / (BN / TN);

    unsigned long long acc2[TM][TN / 2];
    #pragma unroll
    for (int i = 0; i < TM; i++)
        #pragma unroll
        for (int j = 0; j < TN / 2; j++) acc2[i][j] = 0ull;

    const int nT = (Ksz + BK - 1) / BK;
    ldg(0);
    sts(0);
    __syncthreads();

    for (int kt = 0; kt < nT; kt++) {
        int cur = kt & 1;
        if (kt + 1 < nT) ldg((kt + 1) * BK);
        #pragma unroll
        for (int kq = 0; kq < BK; kq++) {
            float ar[TM];
            #pragma unroll
            for (int t = 0; t < TM / 4; t++) {
                float4 a = *(const float4*)&As[cur][kq][ty * TM + 4 * t];
                ar[4 * t + 0] = a.x; ar[4 * t + 1] = a.y;
                ar[4 * t + 2] = a.z; ar[4 * t + 3] = a.w;
            }
            const ulonglong2* pb = (const ulonglong2*)&Bs[cur][kq][tx * TN];
            ulonglong2 q0 = pb[0], q1 = pb[1];
            unsigned long long b2[4] = {q0.x, q0.y, q1.x, q1.y};
            #pragma unroll
            for (int i = 0; i < TM; i++) {
                unsigned long long af = pack_dup_f32(ar[i]);
                #pragma unroll
                for (int j = 0; j < TN / 2; j++) fma_f32x2(acc2[i][j], af, b2[j]);
            }
        }
        if (kt + 1 < nT) {
            sts(cur ^ 1);
            __syncthreads();
        }
    }

    float rr[KEXP];
    #pragma unroll
    for (int k = 0; k < KEXP; k++) rr[k] = R[b * KEXP + k];
    #pragma unroll
    for (int i = 0; i < TM; i++) {
        int gm = m0 + ty * TM + i;
        if (gm < Cout) {
            float bias = 0.f;
            #pragma unroll
            for (int k = 0; k < KEXP; k++) bias += rr[k] * BEXP[k * Cout + gm];
            float* Yp = Y + ((size_t)b * Cout + gm) * Nn;
            #pragma unroll
            for (int j = 0; j < TN / 2; j++) {
                float lo, hi;
                unpack_f32x2(acc2[i][j], lo, hi);
                int gn = n0 + tx * TN + 2 * j;
                if (gn < Nn) {
                    float v = lo + bias;
                    Yp[gn] = v > 0.f ? v : 0.f;
                }
                if (gn + 1 < Nn) {
                    float v = hi + bias;
                    Yp[gn + 1] = v > 0.f ? v : 0.f;
                }
            }
        }
    }
}

// ---------------- FC split-K partial GEMM (transposed, f32x2) ---------------
__global__ void __launch_bounds__(256) fc_partial_kernel(
    const float* __restrict__ Wm, const float* __restrict__ Xt,
    float* __restrict__ Part, int Nout, int Npad, int Kchunk) {
    constexpr int BM = 128, BN = 128, BK = 16, TM = 8, TN = 8;
    __shared__ float As[2][BK][BM + 4];
    __shared__ float Bs[2][BK][BN + 4];
    const int m0 = blockIdx.x * BM;
    const int ks = blockIdx.y;
    const int kbase = ks * Kchunk;
    const int tid = threadIdx.x;

    const int ma = tid % BM;
    const int ka = tid / BM;
    const bool mvalid = (m0 + ma) < Nout;

    float aT[8], bT[8];
    auto ldg = [&](int kk) {
        #pragma unroll
        for (int p = 0; p < 8; p++) {
            int gk = kbase + kk + ka + 2 * p;
            aT[p] = mvalid ? Wm[(size_t)gk * Nout + m0 + ma] : 0.f;
            bT[p] = Xt[(size_t)gk * 128 + ma];
        }
    };
    auto sts = [&](int buf) {
        #pragma unroll
        for (int p = 0; p < 8; p++) {
            int k = ka + 2 * p;
            As[buf][k][ma] = aT[p];
            Bs[buf][k][ma] = bT[p];
        }
    };

    const int tx = tid % (BN / TN);
    const int ty = tid / (BN / TN);
    unsigned long long acc2[TM][TN / 2];
    #pragma unroll
    for (int i = 0; i < TM; i++)
        #pragma unroll
        for (int j = 0; j < TN / 2; j++) acc2[i][j] = 0ull;

    const int nT = Kchunk / BK;
    ldg(0);
    sts(0);
    __syncthreads();
    for (int kt = 0; kt < nT; kt++) {
        int cur = kt & 1;
        if (kt + 1 < nT) ldg((kt + 1) * BK);
        #pragma unroll
        for (int kq = 0; kq < BK; kq++) {
            float4 a0 = *(const float4*)&As[cur][kq][ty * TM];
            float4 a1 = *(const float4*)&As[cur][kq][ty * TM + 4];
            const ulonglong2* pb = (const ulonglong2*)&Bs[cur][kq][tx * TN];
            ulonglong2 q0 = pb[0], q1 = pb[1];
            unsigned long long b2[4] = {q0.x, q0.y, q1.x, q1.y};
            float ar[8] = {a0.x, a0.y, a0.z, a0.w, a1.x, a1.y, a1.z, a1.w};
            #pragma unroll
            for (int i = 0; i < TM; i++) {
                unsigned long long af = pack_dup_f32(ar[i]);
                #pragma unroll
                for (int j = 0; j < TN / 2; j++) fma_f32x2(acc2[i][j], af, b2[j]);
            }
        }
        if (kt + 1 < nT) {
            sts(cur ^ 1);
            __syncthreads();
        }
    }
    #pragma unroll
    for (int i = 0; i < TM; i++) {
        size_t rrow = (size_t)ks * Npad + m0 + ty * TM + i;
        #pragma unroll
        for (int j = 0; j < TN / 2; j++) {
            float lo, hi;
            unpack_f32x2(acc2[i][j], lo, hi);
            Part[rrow * 128 + tx * TN + 2 * j] = lo;
            Part[rrow * 128 + tx * TN + 2 * j + 1] = hi;
        }
    }
}

__global__ void fc_reduce_kernel(const float* __restrict__ Part, const float* __restrict__ bias,
                                 float* __restrict__ Yt, int Nout, int Npad, int S) {
    int idx = blockIdx.x * blockDim.x + threadIdx.x;
    if (idx >= Nout * 128) return;
    int n = idx >> 7, bb = idx & 127;
    float s = 0.f;
    for (int si = 0; si < S; si++) s += Part[((size_t)si * Npad + n) * 128 + bb];
    float v = s + bias[n];
    Yt[idx] = v > 0.f ? v : 0.f;
}

__global__ void fc_reduce_out_kernel(const float* __restrict__ Part, const float* __restrict__ bias,
                                     float* __restrict__ out, int Nout, int Npad, int S) {
    int idx = blockIdx.x * blockDim.x + threadIdx.x;
    if (idx >= Nout * 128) return;
    int n = idx >> 7, bb = idx & 127;
    float s = 0.f;
    for (int si = 0; si < S; si++) s += Part[((size_t)si * Npad + n) * 128 + bb];
    out[(size_t)bb * Nout + n] = s + bias[n];
}

// ---------------- maxpools ---------------------------------------------------
// fused 3x2 maxpool + per-(b,c) mean of the pooled output (deterministic)
__global__ void maxpool_mean_kernel(const float* __restrict__ x, float* __restrict__ y,
                                    float* __restrict__ pooled,
                                    int C, int H, int W, int OH, int OW) {
    int c = blockIdx.x, b = blockIdx.y;
    const float* p = x + ((size_t)b * C + c) * H * W;
    float* yp = y + ((size_t)b * C + c) * OH * OW;
    const int total = OH * OW;
    float s = 0.f;
    for (int i = threadIdx.x; i < total; i += blockDim.x) {
        int oy = i / OW, ox = i - oy * OW;
        const float* q = p + (size_t)(oy * 2) * W + ox * 2;
        float m = -INFINITY;
        #pragma unroll
        for (int ii = 0; ii < 3; ii++)
            #pragma unroll
            for (int jj = 0; jj < 3; jj++) {
                float v = q[ii * W + jj];
                m = v > m ? v : m;
            }
        yp[i] = m;
        s += m;
    }
    __shared__ float sh[32];
    int lane = threadIdx.x & 31, w = threadIdx.x >> 5;
    #pragma unroll
    for (int o = 16; o > 0; o >>= 1) s += __shfl_down_sync(0xffffffffu, s, o);
    if (lane == 0) sh[w] = s;
    __syncthreads();
    if (w == 0) {
        s = (lane < (int)(blockDim.x >> 5)) ? sh[lane] : 0.f;
        #pragma unroll
        for (int o = 16; o > 0; o >>= 1) s += __shfl_down_sync(0xffffffffu, s, o);
        if (lane == 0) pooled[b * C + c] = s / (float)total;
    }
}

__global__ void maxpoolT_kernel(const float* __restrict__ x, float* __restrict__ yt,
                                int C, int H, int W, int OH, int OW) {
    int idx = blockIdx.x * blockDim.x + threadIdx.x;
    int total = 128 * C * OH * OW;
    if (idx >= total) return;
    int ox = idx % OW; int t = idx / OW;
    int oy = t % OH; t /= OH;
    int c = t % C; int b = t / C;
    const float* p = x + (((size_t)b * C + c) * H + oy * 2) * W + ox * 2;
    float m = -INFINITY;
    #pragma unroll
    for (int i = 0; i < 3; i++)
        #pragma unroll
        for (int j = 0; j < 3; j++) {
            float v = p[i * W + j];
            m = v > m ? v : m;
        }
    yt[((size_t)(c * OH + oy) * OW + ox) * 128 + b] = m;
}

// ---------------- driver -----------------------------------------------------
static inline int ceil_div(int a, int b) { return (a + b - 1) / b; }

extern "C" void kernel_launch(void* const* d_in, const int* in_sizes, int n_in,
                              void* d_out, int out_size) {
    const float* x = (const float*)d_in[0];
    const float *w[5], *bexp[5], *rw[5], *rb[5];
    for (int l = 0; l < 5; l++) {
        w[l]    = (const float*)d_in[1 + 4 * l];
        bexp[l] = (const float*)d_in[2 + 4 * l];
        rw[l]   = (const float*)d_in[3 + 4 * l];
        rb[l]   = (const float*)d_in[4 + 4 * l];
    }
    const float* fw1 = (const float*)d_in[21]; const float* fb1 = (const float*)d_in[22];
    const float* fw2 = (const float*)d_in[23]; const float* fb2 = (const float*)d_in[24];
    const float* fw3 = (const float*)d_in[25]; const float* fb3 = (const float*)d_in[26];

    float *bufA, *bufB, *wbuf, *pooled, *r;
    cudaGetSymbolAddress((void**)&bufA, g_bufA);
    cudaGetSymbolAddress((void**)&bufB, g_bufB);
    cudaGetSymbolAddress((void**)&wbuf, g_wbuf);
    cudaGetSymbolAddress((void**)&pooled, g_pooled);
    cudaGetSymbolAddress((void**)&r, g_r);

    const int B = 128;

    // ===== Layer 1: CondConv 3->64, k=11, s=4, p=2 : 224->55, pool(+mean)->27
    pool_mean_kernel<<<dim3(3, B), 256>>>(x, pooled, 3, 224 * 224);
    routing_kernel<<<B, 256>>>(pooled, rw[0], rb[0], r, 3);
    {
        int ws4 = 64 * 3 * 121 / 4;
        mixw2_kernel<<<dim3(ceil_div(ws4, 256), B / 8), 256>>>((const float4*)w[0], r, (float4*)wbuf, ws4);
    }
    conv2_kernel<64, 128, 8, 11, 11, 4, 2, false, false><<<dim3(24, 1, B), 128>>>(
        x, wbuf, r, bexp[0], bufA, 3, 64, 224, 224, 55, 55);
    maxpool_mean_kernel<<<dim3(64, B), 256>>>(bufA, bufB, pooled, 64, 55, 55, 27, 27);

    // ===== Layer 2: CondConv 64->192, k=5, p=2 : 27->27, pool(+mean)->13
    routing_kernel<<<B, 256>>>(pooled, rw[1], rb[1], r, 64);
    mixw4_kernel<<<dim3(ceil_div(64 * 25, 512), 192), 256>>>(w[1], r, wbuf, 192, 64, 25);
    conv2_kernel<64, 128, 8, 5, 5, 1, 2, true, true><<<dim3(6, 3, B), 128>>>(
        bufB, wbuf, r, bexp[1], bufA, 64, 192, 27, 27, 27, 27);
    maxpool_mean_kernel<<<dim3(192, B), 256>>>(bufA, bufB, pooled, 192, 27, 27, 13, 13);

    // ===== Layer 3: CondConv 192->384, k=3, p=1 : 13->13 (BM=128, 1152 CTAs)
    routing_kernel<<<B, 256>>>(pooled, rw[2], rb[2], r, 192);
    mixw4_kernel<<<dim3(ceil_div(192 * 9, 512), 384), 256>>>(w[2], r, wbuf, 384, 192, 9);
    conv2_kernel<128, 64, 8, 3, 3, 1, 1, true, true><<<dim3(3, 3, B), 128>>>(
        bufB, wbuf, r, bexp[2], bufA, 192, 384, 13, 13, 13, 13);

    // ===== Layer 4: CondConv 384->256, k=3, p=1 : 13->13 (BM=64 fine-grain)
    pool_mean_kernel<<<dim3(384, B), 256>>>(bufA, pooled, 384, 13 * 13);
    routing_kernel<<<B, 256>>>(pooled, rw[3], rb[3], r, 384);
    mixw4_kernel<<<dim3(ceil_div(384 * 9, 512), 256), 256>>>(w[3], r, wbuf, 256, 384, 9);
    conv2_kernel<64, 64, 4, 3, 3, 1, 1, true, true><<<dim3(3, 4, B), 128>>>(
        bufA, wbuf, r, bexp[3], bufB, 384, 256, 13, 13, 13, 13);

    // ===== Layer 5: CondConv 256->256, k=3, p=1 : 13->13, pool->6 (BM=64)
    pool_mean_kernel<<<dim3(256, B), 256>>>(bufB, pooled, 256, 13 * 13);
    routing_kernel<<<B, 256>>>(pooled, rw[4], rb[4], r, 256);
    mixw4_kernel<<<dim3(ceil_div(256 * 9, 512), 256), 256>>>(w[4], r, wbuf, 256, 256, 9);
    conv2_kernel<64, 64, 4, 3, 3, 1, 1, true, true><<<dim3(3, 4, B), 128>>>(
        bufB, wbuf, r, bexp[4], bufA, 256, 256, 13, 13, 13, 13);

    // final pool -> transposed activations [9216][128]
    maxpoolT_kernel<<<ceil_div(B * 256 * 36, 256), 256>>>(bufA, wbuf + POOLT_OFF, 256, 13, 13, 6, 6);

    // ===== FC head (fp32, split-K, S=8) =====================================
    fc_partial_kernel<<<dim3(32, 8), 256>>>(fw1, wbuf + POOLT_OFF, wbuf + PART_OFF,
                                            4096, 4096, 1152);
    fc_reduce_kernel<<<ceil_div(4096 * 128, 256), 256>>>(wbuf + PART_OFF, fb1,
                                                         wbuf + Y1T_OFF, 4096, 4096, 8);
    fc_partial_kernel<<<dim3(32, 8), 256>>>(fw2, wbuf + Y1T_OFF, wbuf + PART_OFF,
                                            4096, 4096, 512);
    fc_reduce_kernel<<<ceil_div(4096 * 128, 256), 256>>>(wbuf + PART_OFF, fb2,
                                                         wbuf + Y2T_OFF, 4096, 4096, 8);
    fc_partial_kernel<<<dim3(8, 8), 256>>>(fw3, wbuf + Y2T_OFF, wbuf + PART_OFF,
                                           1000, 1024, 512);
    fc_reduce_out_kernel<<<ceil_div(1000 * 128, 256), 256>>>(wbuf + PART_OFF, fb3,
                                                             (float*)d_out, 1000, 1024, 8);
}

// round 17
// speedup vs baseline: 1.5980x; 1.1335x over previous
#include <cuda_runtime.h>
#include <math.h>
#include <stdint.h>

#define KEXP 8

// ---------------- scratch (static device memory; no allocations allowed) ----
__device__ float g_bufA[24780800];    // max: act1 = 128*64*55*55
__device__ float g_bufB[5971968];     // max: pool1 = 128*64*27*27
__device__ float g_wbuf[113246208];   // max: L4 mixed weights; FC scratch later
__device__ float g_pooled[128 * 384];
__device__ float g_r[128 * KEXP];

// FC scratch offsets inside g_wbuf (in floats)
#define POOLT_OFF 0
#define PART_OFF  (2*1024*1024)
#define Y1T_OFF   (7*1024*1024)
#define Y2T_OFF   (8*1024*1024)

// ---------------- packed fp32x2 FMA helpers ----------------------------------
__device__ __forceinline__ unsigned long long pack_dup_f32(float a) {
    unsigned long long p;
    asm("mov.b64 %0, {%1, %1};" : "=l"(p) : "f"(a));
    return p;
}
__device__ __forceinline__ void fma_f32x2(unsigned long long& d, unsigned long long a,
                                          unsigned long long b) {
    asm("fma.rn.f32x2 %0, %1, %2, %0;" : "+l"(d) : "l"(a), "l"(b));
}
__device__ __forceinline__ void unpack_f32x2(unsigned long long p, float& lo, float& hi) {
    asm("mov.b64 {%0, %1}, %2;" : "=f"(lo), "=f"(hi) : "l"(p));
}

// ---------------- per-channel global average pool ---------------------------
__global__ void pool_mean_kernel(const float* __restrict__ x, float* __restrict__ pooled,
                                 int Cin, int HW) {
    int c = blockIdx.x, b = blockIdx.y;
    const float* p = x + ((size_t)b * Cin + c) * HW;
    float s = 0.f;
    for (int i = threadIdx.x; i < HW; i += blockDim.x) s += p[i];
    __shared__ float sh[32];
    int lane = threadIdx.x & 31, w = threadIdx.x >> 5;
    #pragma unroll
    for (int o = 16; o > 0; o >>= 1) s += __shfl_down_sync(0xffffffffu, s, o);
    if (lane == 0) sh[w] = s;
    __syncthreads();
    if (w == 0) {
        s = (lane < (int)(blockDim.x >> 5)) ? sh[lane] : 0.f;
        #pragma unroll
        for (int o = 16; o > 0; o >>= 1) s += __shfl_down_sync(0xffffffffu, s, o);
        if (lane == 0) pooled[b * Cin + c] = s / (float)HW;
    }
}

// ---------------- routing ----------------------------------------------------
__global__ void routing_kernel(const float* __restrict__ pooled, const float* __restrict__ rw,
                               const float* __restrict__ rb, float* __restrict__ r, int Cin) {
    int b = blockIdx.x;
    int k = threadIdx.x >> 5, lane = threadIdx.x & 31;
    if (k < KEXP) {
        float s = 0.f;
        for (int c = lane; c < Cin; c += 32) s += pooled[b * Cin + c] * rw[c * KEXP + k];
        #pragma unroll
        for (int o = 16; o > 0; o >>= 1) s += __shfl_down_sync(0xffffffffu, s, o);
        if (lane == 0) r[b * KEXP + k] = 1.f / (1.f + expf(-(s + rb[k])));
    }
}

// ---------------- expert weight mixing (layer 1: original [ci][khw] order) ---
__global__ void mixw2_kernel(const float4* __restrict__ w, const float* __restrict__ r,
                             float4* __restrict__ wb, int ws4) {
    __shared__ float rs[8][KEXP];
    int bg = blockIdx.y;
    if (threadIdx.x < 64)
        rs[threadIdx.x >> 3][threadIdx.x & 7] =
            r[(bg * 8 + (threadIdx.x >> 3)) * KEXP + (threadIdx.x & 7)];
    __syncthreads();
    int i = blockIdx.x * blockDim.x + threadIdx.x;
    if (i >= ws4) return;
    float4 wv[KEXP];
    #pragma unroll
    for (int k = 0; k < KEXP; k++) wv[k] = w[(size_t)k * ws4 + i];
    #pragma unroll
    for (int bb = 0; bb < 8; bb++) {
        float4 acc = make_float4(0.f, 0.f, 0.f, 0.f);
        #pragma unroll
        for (int k = 0; k < KEXP; k++) {
            float rk = rs[bb][k];
            acc.x += rk * wv[k].x; acc.y += rk * wv[k].y;
            acc.z += rk * wv[k].z; acc.w += rk * wv[k].w;
        }
        wb[(size_t)(bg * 8 + bb) * ws4 + i] = acc;
    }
}

// ---------------- mixing + K-transpose, read-once over full batch ------------
// in:  w[k][co][ci][khw]   out: wb[b][co][khw*Cin + ci]  (khw-major, ci fastest)
__global__ void __launch_bounds__(256) mixw4_kernel(
    const float* __restrict__ w, const float* __restrict__ r,
    float* __restrict__ wb, int Cout, int Cin, int KHW) {
    const int Ksz = Cin * KHW;
    const int co = blockIdx.y;
    const int o = blockIdx.x * 512 + threadIdx.x * 2;

    __shared__ float rs[128][KEXP];
    for (int i = threadIdx.x; i < 128 * KEXP; i += 256)
        rs[i >> 3][i & 7] = r[i];
    __syncthreads();

    if (o >= Ksz) return;
    const bool has2 = (o + 1) < Ksz;

    const int khw0 = o / Cin, ci0 = o - khw0 * Cin;
    const int khw1 = (o + 1) / Cin, ci1 = (o + 1) - khw1 * Cin;
    const size_t ws = (size_t)Cout * Ksz;
    const float* p0 = w + (size_t)co * Ksz + (size_t)ci0 * KHW + khw0;
    const float* p1 = w + (size_t)co * Ksz + (size_t)ci1 * KHW + khw1;

    float wv0[KEXP], wv1[KEXP];
    #pragma unroll
    for (int k = 0; k < KEXP; k++) {
        wv0[k] = p0[(size_t)k * ws];
        wv1[k] = has2 ? p1[(size_t)k * ws] : 0.f;
    }

    float* out0 = wb + (size_t)co * Ksz + o;
    const size_t bstride = (size_t)Cout * Ksz;
    for (int b = 0; b < 128; b++) {
        float a0 = 0.f, a1 = 0.f;
        #pragma unroll
        for (int k = 0; k < KEXP; k++) {
            float rk = rs[b][k];
            a0 += rk * wv0[k];
            a1 += rk * wv1[k];
        }
        float* out = out0 + (size_t)b * bstride;
        if (has2) *reinterpret_cast<float2*>(out) = make_float2(a0, a1);
        else out[0] = a0;
    }
}

// ============================================================================
// SIMT conv implicit GEMM, f32x2 FMA, double-buffered (R3/R8 proven core).
// CIN_INNER: mixed weights are [khw][ci]; every BK=16 chunk lies in ONE (ky,kx).
// ============================================================================
template <int BM, int BN, int TM, int KH, int KW, int S, int P, bool AVEC, bool CIN_INNER>
__global__ void __launch_bounds__(128) conv2_kernel(
    const float* __restrict__ X, const float* __restrict__ WB,
    const float* __restrict__ R, const float* __restrict__ BEXP,
    float* __restrict__ Y, int Cin, int Cout, int H, int W, int OH, int OW) {
    constexpr int BK = 16, TN = 8;
    constexpr int TH = BM * BN / (TM * TN);   // must be 128
    static_assert(TH == 128, "128 threads");
    constexpr int KHW = KH * KW;
    constexpr int A4 = BM * BK / (4 * TH);
    constexpr int BL = BN * BK / TH;
    constexpr int BKP = TH / BN;

    __shared__ float As[2][BK][BM + 4];
    __shared__ float Bs[2][BK][BN + 4];

    const int b = blockIdx.z;
    const int m0 = blockIdx.y * BM, n0 = blockIdx.x * BN;
    const int Ksz = Cin * KHW;
    const int Nn = OH * OW;
    const int HWp = H * W;
    const int tid = threadIdx.x;

    const float* __restrict__ Xb = X + (size_t)b * Cin * HWp;
    const float* __restrict__ Wb = WB + (size_t)b * Cout * Ksz;

    const int nb = tid % BN;
    const int gnb = n0 + nb;
    const bool nv = gnb < Nn;
    const int oyb = nv ? gnb / OW : 0;
    const int oxb = nv ? gnb - oyb * OW : 0;
    const int iy0 = oyb * S - P, ix0 = oxb * S - P;
    const int kb0 = tid / BN;

    float4 aT[A4];
    float bT[BL];

    auto ldg = [&](int kk) {
        #pragma unroll
        for (int p = 0; p < A4; p++) {
            int e = tid + p * TH;
            int m = e >> 2, gk = kk + (e & 3) * 4;
            float4 v = make_float4(0.f, 0.f, 0.f, 0.f);
            if (m0 + m < Cout) {
                if (AVEC && (CIN_INNER || gk + 3 < Ksz)) {
                    v = *reinterpret_cast<const float4*>(Wb + (size_t)(m0 + m) * Ksz + gk);
                } else {
                    float* pv = (float*)&v;
                    #pragma unroll
                    for (int i = 0; i < 4; i++)
                        if (gk + i < Ksz) pv[i] = Wb[(size_t)(m0 + m) * Ksz + gk + i];
                }
            }
            aT[p] = v;
        }
        if (CIN_INNER) {
            int khw = kk / Cin;
            int ci0 = kk - khw * Cin;
            int ky = khw / KW, kx = khw - ky * KW;
            int iy = iy0 + ky, ix = ix0 + kx;
            bool rowv = nv && iy >= 0 && iy < H && ix >= 0 && ix < W;
            const float* src = Xb + (size_t)iy * W + ix;
            #pragma unroll
            for (int p = 0; p < BL; p++) {
                int ci = ci0 + kb0 + p * BKP;
                bT[p] = rowv ? src[(size_t)ci * HWp] : 0.f;
            }
        } else {
            #pragma unroll
            for (int p = 0; p < BL; p++) {
                int k = kb0 + p * BKP;
                int gk = kk + k;
                float v = 0.f;
                if (nv && gk < Ksz) {
                    int ci = gk / KHW;
                    int rem = gk - ci * KHW;
                    int ky = rem / KW, kx = rem - ky * KW;
                    int iy = iy0 + ky, ix = ix0 + kx;
                    if (iy >= 0 && iy < H && ix >= 0 && ix < W)
                        v = Xb[((size_t)ci * H + iy) * W + ix];
                }
                bT[p] = v;
            }
        }
    };
    auto sts = [&](int buf) {
        #pragma unroll
        for (int p = 0; p < A4; p++) {
            int e = tid + p * TH;
            int m = e >> 2, k = (e & 3) * 4;
            As[buf][k + 0][m] = aT[p].x;
            As[buf][k + 1][m] = aT[p].y;
            As[buf][k + 2][m] = aT[p].z;
            As[buf][k + 3][m] = aT[p].w;
        }
        #pragma unroll
        for (int p = 0; p < BL; p++) Bs[buf][kb0 + p * BKP][nb] = bT[p];
    };

    const int tx = tid % (BN / TN);
    const int ty = tid / (BN / TN);

    unsigned long long acc2[TM][TN / 2];
    #pragma unroll
    for (int i = 0; i < TM; i++)
        #pragma unroll
        for (int j = 0; j < TN / 2; j++) acc2[i][j] = 0ull;

    const int nT = (Ksz + BK - 1) / BK;
    ldg(0);
    sts(0);
    __syncthreads();

    for (int kt = 0; kt < nT; kt++) {
        int cur = kt & 1;
        if (kt + 1 < nT) ldg((kt + 1) * BK);
        #pragma unroll
        for (int kq = 0; kq < BK; kq++) {
            float ar[TM];
            #pragma unroll
            for (int t = 0; t < TM / 4; t++) {
                float4 a = *(const float4*)&As[cur][kq][ty * TM + 4 * t];
                ar[4 * t + 0] = a.x; ar[4 * t + 1] = a.y;
                ar[4 * t + 2] = a.z; ar[4 * t + 3] = a.w;
            }
            const ulonglong2* pb = (const ulonglong2*)&Bs[cur][kq][tx * TN];
            ulonglong2 q0 = pb[0], q1 = pb[1];
            unsigned long long b2[4] = {q0.x, q0.y, q1.x, q1.y};
            #pragma unroll
            for (int i = 0; i < TM; i++) {
                unsigned long long af = pack_dup_f32(ar[i]);
                #pragma unroll
                for (int j = 0; j < TN / 2; j++) fma_f32x2(acc2[i][j], af, b2[j]);
            }
        }
        if (kt + 1 < nT) {
            sts(cur ^ 1);
            __syncthreads();
        }
    }

    float rr[KEXP];
    #pragma unroll
    for (int k = 0; k < KEXP; k++) rr[k] = R[b * KEXP + k];
    #pragma unroll
    for (int i = 0; i < TM; i++) {
        int gm = m0 + ty * TM + i;
        if (gm < Cout) {
            float bias = 0.f;
            #pragma unroll
            for (int k = 0; k < KEXP; k++) bias += rr[k] * BEXP[k * Cout + gm];
            float* Yp = Y + ((size_t)b * Cout + gm) * Nn;
            #pragma unroll
            for (int j = 0; j < TN / 2; j++) {
                float lo, hi;
                unpack_f32x2(acc2[i][j], lo, hi);
                int gn = n0 + tx * TN + 2 * j;
                if (gn < Nn) {
                    float v = lo + bias;
                    Yp[gn] = v > 0.f ? v : 0.f;
                }
                if (gn + 1 < Nn) {
                    float v = hi + bias;
                    Yp[gn + 1] = v > 0.f ? v : 0.f;
                }
            }
        }
    }
}

// ---------------- FC split-K partial GEMM (transposed, f32x2) ---------------
__global__ void __launch_bounds__(256) fc_partial_kernel(
    const float* __restrict__ Wm, const float* __restrict__ Xt,
    float* __restrict__ Part, int Nout, int Npad, int Kchunk) {
    constexpr int BM = 128, BN = 128, BK = 16, TM = 8, TN = 8;
    __shared__ float As[2][BK][BM + 4];
    __shared__ float Bs[2][BK][BN + 4];
    const int m0 = blockIdx.x * BM;
    const int ks = blockIdx.y;
    const int kbase = ks * Kchunk;
    const int tid = threadIdx.x;

    const int ma = tid % BM;
    const int ka = tid / BM;
    const bool mvalid = (m0 + ma) < Nout;

    float aT[8], bT[8];
    auto ldg = [&](int kk) {
        #pragma unroll
        for (int p = 0; p < 8; p++) {
            int gk = kbase + kk + ka + 2 * p;
            aT[p] = mvalid ? Wm[(size_t)gk * Nout + m0 + ma] : 0.f;
            bT[p] = Xt[(size_t)gk * 128 + ma];
        }
    };
    auto sts = [&](int buf) {
        #pragma unroll
        for (int p = 0; p < 8; p++) {
            int k = ka + 2 * p;
            As[buf][k][ma] = aT[p];
            Bs[buf][k][ma] = bT[p];
        }
    };

    const int tx = tid % (BN / TN);
    const int ty = tid / (BN / TN);
    unsigned long long acc2[TM][TN / 2];
    #pragma unroll
    for (int i = 0; i < TM; i++)
        #pragma unroll
        for (int j = 0; j < TN / 2; j++) acc2[i][j] = 0ull;

    const int nT = Kchunk / BK;
    ldg(0);
    sts(0);
    __syncthreads();
    for (int kt = 0; kt < nT; kt++) {
        int cur = kt & 1;
        if (kt + 1 < nT) ldg((kt + 1) * BK);
        #pragma unroll
        for (int kq = 0; kq < BK; kq++) {
            float4 a0 = *(const float4*)&As[cur][kq][ty * TM];
            float4 a1 = *(const float4*)&As[cur][kq][ty * TM + 4];
            const ulonglong2* pb = (const ulonglong2*)&Bs[cur][kq][tx * TN];
            ulonglong2 q0 = pb[0], q1 = pb[1];
            unsigned long long b2[4] = {q0.x, q0.y, q1.x, q1.y};
            float ar[8] = {a0.x, a0.y, a0.z, a0.w, a1.x, a1.y, a1.z, a1.w};
            #pragma unroll
            for (int i = 0; i < TM; i++) {
                unsigned long long af = pack_dup_f32(ar[i]);
                #pragma unroll
                for (int j = 0; j < TN / 2; j++) fma_f32x2(acc2[i][j], af, b2[j]);
            }
        }
        if (kt + 1 < nT) {
            sts(cur ^ 1);
            __syncthreads();
        }
    }
    #pragma unroll
    for (int i = 0; i < TM; i++) {
        size_t rrow = (size_t)ks * Npad + m0 + ty * TM + i;
        #pragma unroll
        for (int j = 0; j < TN / 2; j++) {
            float lo, hi;
            unpack_f32x2(acc2[i][j], lo, hi);
            Part[rrow * 128 + tx * TN + 2 * j] = lo;
            Part[rrow * 128 + tx * TN + 2 * j + 1] = hi;
        }
    }
}

__global__ void fc_reduce_kernel(const float* __restrict__ Part, const float* __restrict__ bias,
                                 float* __restrict__ Yt, int Nout, int Npad, int S) {
    int idx = blockIdx.x * blockDim.x + threadIdx.x;
    if (idx >= Nout * 128) return;
    int n = idx >> 7, bb = idx & 127;
    float s = 0.f;
    for (int si = 0; si < S; si++) s += Part[((size_t)si * Npad + n) * 128 + bb];
    float v = s + bias[n];
    Yt[idx] = v > 0.f ? v : 0.f;
}

__global__ void fc_reduce_out_kernel(const float* __restrict__ Part, const float* __restrict__ bias,
                                     float* __restrict__ out, int Nout, int Npad, int S) {
    int idx = blockIdx.x * blockDim.x + threadIdx.x;
    if (idx >= Nout * 128) return;
    int n = idx >> 7, bb = idx & 127;
    float s = 0.f;
    for (int si = 0; si < S; si++) s += Part[((size_t)si * Npad + n) * 128 + bb];
    out[(size_t)bb * Nout + n] = s + bias[n];
}

// ---------------- maxpools ---------------------------------------------------
// fused 3x2 maxpool + per-(b,c) mean of the pooled output (deterministic)
__global__ void maxpool_mean_kernel(const float* __restrict__ x, float* __restrict__ y,
                                    float* __restrict__ pooled,
                                    int C, int H, int W, int OH, int OW) {
    int c = blockIdx.x, b = blockIdx.y;
    const float* p = x + ((size_t)b * C + c) * H * W;
    float* yp = y + ((size_t)b * C + c) * OH * OW;
    const int total = OH * OW;
    float s = 0.f;
    for (int i = threadIdx.x; i < total; i += blockDim.x) {
        int oy = i / OW, ox = i - oy * OW;
        const float* q = p + (size_t)(oy * 2) * W + ox * 2;
        float m = -INFINITY;
        #pragma unroll
        for (int ii = 0; ii < 3; ii++)
            #pragma unroll
            for (int jj = 0; jj < 3; jj++) {
                float v = q[ii * W + jj];
                m = v > m ? v : m;
            }
        yp[i] = m;
        s += m;
    }
    __shared__ float sh[32];
    int lane = threadIdx.x & 31, w = threadIdx.x >> 5;
    #pragma unroll
    for (int o = 16; o > 0; o >>= 1) s += __shfl_down_sync(0xffffffffu, s, o);
    if (lane == 0) sh[w] = s;
    __syncthreads();
    if (w == 0) {
        s = (lane < (int)(blockDim.x >> 5)) ? sh[lane] : 0.f;
        #pragma unroll
        for (int o = 16; o > 0; o >>= 1) s += __shfl_down_sync(0xffffffffu, s, o);
        if (lane == 0) pooled[b * C + c] = s / (float)total;
    }
}

__global__ void maxpoolT_kernel(const float* __restrict__ x, float* __restrict__ yt,
                                int C, int H, int W, int OH, int OW) {
    int idx = blockIdx.x * blockDim.x + threadIdx.x;
    int total = 128 * C * OH * OW;
    if (idx >= total) return;
    int ox = idx % OW; int t = idx / OW;
    int oy = t % OH; t /= OH;
    int c = t % C; int b = t / C;
    const float* p = x + (((size_t)b * C + c) * H + oy * 2) * W + ox * 2;
    float m = -INFINITY;
    #pragma unroll
    for (int i = 0; i < 3; i++)
        #pragma unroll
        for (int j = 0; j < 3; j++) {
            float v = p[i * W + j];
            m = v > m ? v : m;
        }
    yt[((size_t)(c * OH + oy) * OW + ox) * 128 + b] = m;
}

// ---------------- driver -----------------------------------------------------
static inline int ceil_div(int a, int b) { return (a + b - 1) / b; }

extern "C" void kernel_launch(void* const* d_in, const int* in_sizes, int n_in,
                              void* d_out, int out_size) {
    const float* x = (const float*)d_in[0];
    const float *w[5], *bexp[5], *rw[5], *rb[5];
    for (int l = 0; l < 5; l++) {
        w[l]    = (const float*)d_in[1 + 4 * l];
        bexp[l] = (const float*)d_in[2 + 4 * l];
        rw[l]   = (const float*)d_in[3 + 4 * l];
        rb[l]   = (const float*)d_in[4 + 4 * l];
    }
    const float* fw1 = (const float*)d_in[21]; const float* fb1 = (const float*)d_in[22];
    const float* fw2 = (const float*)d_in[23]; const float* fb2 = (const float*)d_in[24];
    const float* fw3 = (const float*)d_in[25]; const float* fb3 = (const float*)d_in[26];

    float *bufA, *bufB, *wbuf, *pooled, *r;
    cudaGetSymbolAddress((void**)&bufA, g_bufA);
    cudaGetSymbolAddress((void**)&bufB, g_bufB);
    cudaGetSymbolAddress((void**)&wbuf, g_wbuf);
    cudaGetSymbolAddress((void**)&pooled, g_pooled);
    cudaGetSymbolAddress((void**)&r, g_r);

    const int B = 128;

    // ===== Layer 1: CondConv 3->64, k=11, s=4, p=2 : 224->55, pool(+mean)->27
    pool_mean_kernel<<<dim3(3, B), 256>>>(x, pooled, 3, 224 * 224);
    routing_kernel<<<B, 256>>>(pooled, rw[0], rb[0], r, 3);
    {
        int ws4 = 64 * 3 * 121 / 4;
        mixw2_kernel<<<dim3(ceil_div(ws4, 256), B / 8), 256>>>((const float4*)w[0], r, (float4*)wbuf, ws4);
    }
    conv2_kernel<64, 128, 8, 11, 11, 4, 2, false, false><<<dim3(24, 1, B), 128>>>(
        x, wbuf, r, bexp[0], bufA, 3, 64, 224, 224, 55, 55);
    maxpool_mean_kernel<<<dim3(64, B), 256>>>(bufA, bufB, pooled, 64, 55, 55, 27, 27);

    // ===== Layer 2: CondConv 64->192, k=5, p=2 : 27->27, pool(+mean)->13
    routing_kernel<<<B, 256>>>(pooled, rw[1], rb[1], r, 64);
    mixw4_kernel<<<dim3(ceil_div(64 * 25, 512), 192), 256>>>(w[1], r, wbuf, 192, 64, 25);
    conv2_kernel<64, 128, 8, 5, 5, 1, 2, true, true><<<dim3(6, 3, B), 128>>>(
        bufB, wbuf, r, bexp[1], bufA, 64, 192, 27, 27, 27, 27);
    maxpool_mean_kernel<<<dim3(192, B), 256>>>(bufA, bufB, pooled, 192, 27, 27, 13, 13);

    // ===== Layer 3: CondConv 192->384, k=3, p=1 : 13->13
    routing_kernel<<<B, 256>>>(pooled, rw[2], rb[2], r, 192);
    mixw4_kernel<<<dim3(ceil_div(192 * 9, 512), 384), 256>>>(w[2], r, wbuf, 384, 192, 9);
    conv2_kernel<128, 64, 8, 3, 3, 1, 1, true, true><<<dim3(3, 3, B), 128>>>(
        bufB, wbuf, r, bexp[2], bufA, 192, 384, 13, 13, 13, 13);

    // ===== Layer 4: CondConv 384->256, k=3, p=1 : 13->13
    pool_mean_kernel<<<dim3(384, B), 256>>>(bufA, pooled, 384, 13 * 13);
    routing_kernel<<<B, 256>>>(pooled, rw[3], rb[3], r, 384);
    mixw4_kernel<<<dim3(ceil_div(384 * 9, 512), 256), 256>>>(w[3], r, wbuf, 256, 384, 9);
    conv2_kernel<128, 64, 8, 3, 3, 1, 1, true, true><<<dim3(3, 2, B), 128>>>(
        bufA, wbuf, r, bexp[3], bufB, 384, 256, 13, 13, 13, 13);

    // ===== Layer 5: CondConv 256->256, k=3, p=1 : 13->13, pool->6
    pool_mean_kernel<<<dim3(256, B), 256>>>(bufB, pooled, 256, 13 * 13);
    routing_kernel<<<B, 256>>>(pooled, rw[4], rb[4], r, 256);
    mixw4_kernel<<<dim3(ceil_div(256 * 9, 512), 256), 256>>>(w[4], r, wbuf, 256, 256, 9);
    conv2_kernel<128, 64, 8, 3, 3, 1, 1, true, true><<<dim3(3, 2, B), 128>>>(
        bufB, wbuf, r, bexp[4], bufA, 256, 256, 13, 13, 13, 13);

    // final pool -> transposed activations [9216][128]
    maxpoolT_kernel<<<ceil_div(B * 256 * 36, 256), 256>>>(bufA, wbuf + POOLT_OFF, 256, 13, 13, 6, 6);

    // ===== FC head (fp32, split-K, S=8) =====================================
    fc_partial_kernel<<<dim3(32, 8), 256>>>(fw1, wbuf + POOLT_OFF, wbuf + PART_OFF,
                                            4096, 4096, 1152);
    fc_reduce_kernel<<<ceil_div(4096 * 128, 256), 256>>>(wbuf + PART_OFF, fb1,
                                                         wbuf + Y1T_OFF, 4096, 4096, 8);
    fc_partial_kernel<<<dim3(32, 8), 256>>>(fw2, wbuf + Y1T_OFF, wbuf + PART_OFF,
                                            4096, 4096, 512);
    fc_reduce_kernel<<<ceil_div(4096 * 128, 256), 256>>>(wbuf + PART_OFF, fb2,
                                                         wbuf + Y2T_OFF, 4096, 4096, 8);
    fc_partial_kernel<<<dim3(8, 8), 256>>>(fw3, wbuf + Y2T_OFF, wbuf + PART_OFF,
                                           1000, 1024, 512);
    fc_reduce_out_kernel<<<ceil_div(1000 * 128, 256), 256>>>(wbuf + PART_OFF, fb3,
                                                             (float*)d_out, 1000, 1024, 8);
}